// round 15
// baseline (speedup 1.0000x reference)
#include <cuda_runtime.h>
#include <cuda_bf16.h>
#include <math.h>
#include <stdint.h>

// Problem dims
#define Bsz 2
#define Sq  2048
#define Dm  1024
#define Hh  16
#define DHd 64
#define DRr 16
#define SDd 48
#define DCc 128
#define BS  (Bsz*Sq)   // 4096

// ---------------- device scratch (no allocs allowed) ----------------
__device__ float g_T1[(size_t)BS*512];
__device__ float g_T2[(size_t)BS*2816];
__device__ float g_bc1[512];
__device__ float g_bc2[2816];
__device__ float g_part[2*32*128];
__device__ float g_Vsum[2*1024];
// bf16-split weights, FRAGMENT-ORDERED: [colblock][panel][4096 elems]
__device__ __nv_bfloat16 g_W1h[512*1024],  g_W1l[512*1024];    // 4 cb x 32 p
__device__ __nv_bfloat16 g_W2h[2816*128],  g_W2l[2816*128];    // 22 cb x 4 p
__device__ __nv_bfloat16 g_Woh[1024*1024], g_Wol[1024*1024];   // 8 cb x 32 p
// bf16-split ACTIVATION images (A-operands), fragment-ordered [rowblock][panel][4096]
__device__ __nv_bfloat16 g_T1s1h[(size_t)BS*128], g_T1s1l[(size_t)BS*128];  // c_kv
__device__ __nv_bfloat16 g_T1s2h[(size_t)BS*128], g_T1s2l[(size_t)BS*128];  // c_q
__device__ __nv_bfloat16 g_Osh[(size_t)BS*1024],  g_Osl[(size_t)BS*1024];   // attn out
// bf16 attention operand images
__device__ __nv_bfloat16 g_Qb[(size_t)Bsz*Hh*Sq*64];   // A-images per (b,h,qtile): 2 panels x 4096
__device__ __nv_bfloat16 g_Kb[(size_t)Bsz*Hh*Sq*64];   // B-images per (b,h,ktile): 4096 elems
__device__ __nv_bfloat16 g_Vb[(size_t)Bsz*Hh*Sq*64];   // V bf16 B-images

// ---------------- helpers ----------------
__device__ __forceinline__ void mma_bf16(float c[4], const unsigned a[4],
                                         unsigned b0, unsigned b1) {
    asm volatile(
        "mma.sync.aligned.m16n8k16.row.col.f32.bf16.bf16.f32 "
        "{%0,%1,%2,%3}, {%4,%5,%6,%7}, {%8,%9}, {%0,%1,%2,%3};"
        : "+f"(c[0]), "+f"(c[1]), "+f"(c[2]), "+f"(c[3])
        : "r"(a[0]), "r"(a[1]), "r"(a[2]), "r"(a[3]), "r"(b0), "r"(b1));
}
__device__ __forceinline__ unsigned smem_u32(const void* p) {
    unsigned a;
    asm("{ .reg .u64 t; cvta.to.shared.u64 t, %1; cvt.u32.u64 %0, t; }" : "=r"(a) : "l"(p));
    return a;
}
__device__ __forceinline__ void sts64(unsigned addr, unsigned a, unsigned b) {
    asm volatile("st.shared.v2.b32 [%0], {%1,%2};" :: "r"(addr), "r"(a), "r"(b));
}
__device__ __forceinline__ uint2 lds64(unsigned addr) {
    uint2 v;
    asm volatile("ld.shared.v2.b32 {%0,%1}, [%2];" : "=r"(v.x), "=r"(v.y) : "r"(addr));
    return v;
}
__device__ __forceinline__ unsigned bits2(__nv_bfloat162 v) {
    return *reinterpret_cast<unsigned*>(&v);
}
#define CP_ASYNC16(sm, gp) \
    asm volatile("cp.async.cg.shared.global [%0], [%1], 16;" :: "r"(sm), "l"(gp) : "memory")
#define CP_COMMIT() asm volatile("cp.async.commit_group;" ::: "memory")
#define CP_WAIT0()  asm volatile("cp.async.wait_group 0;" ::: "memory")
#define CP_WAIT1()  asm volatile("cp.async.wait_group 1;" ::: "memory")

__device__ __forceinline__ void split_store(__nv_bfloat16* ih, __nv_bfloat16* il,
                                            size_t eo, float x, float y) {
    __nv_bfloat162 hp = __floats2bfloat162_rn(x, y);
    float h0 = __bfloat162float(__low2bfloat16(hp));
    float h1 = __bfloat162float(__high2bfloat16(hp));
    __nv_bfloat162 lp = __floats2bfloat162_rn(x - h0, y - h1);
    *(__nv_bfloat162*)(ih + eo) = hp;
    *(__nv_bfloat162*)(il + eo) = lp;
}

// element offset of (r,k) in a frag-ordered A image with P k-panels (k even)
__device__ __forceinline__ size_t frag_off(int r, int k, int P) {
    return ((size_t)(r >> 7) * P + (k >> 5)) * 4096
         + (size_t)(((((k >> 4) & 1) * 8 + ((r >> 4) & 7)) * 2 + ((r >> 3) & 1)) * 128)
         + (size_t)(((r & 7) * 4 + ((k >> 1) & 3)) * 4) + (size_t)(((k >> 3) & 1) * 2);
}
// element offset of (n,k) in a 64-col B frag image (per-tile 4096 elems)
__device__ __forceinline__ size_t bfrag_off(int n, int k) {
    return (size_t)((k >> 5) * 2048)
         + (size_t)((((k >> 4) & 1) * 8 + (n >> 3)) * 128)
         + (size_t)(((n & 7) * 4 + ((k >> 1) & 3)) * 4)
         + (size_t)(((k >> 3) & 1) * 2) + (size_t)(k & 1);
}

// ---------------- merged weight transpose/split -> fragment-ordered gmem ----------------
__global__ void wsplit_all(const float* __restrict__ Wdkv, const float* __restrict__ Wdq,
                           const float* __restrict__ Wkr,  const float* __restrict__ Wuk,
                           const float* __restrict__ Wuv,  const float* __restrict__ Wuq,
                           const float* __restrict__ Wqr,  const float* __restrict__ Wo,
                           const float* __restrict__ bdkv, const float* __restrict__ bdq,
                           const float* __restrict__ bkr,  const float* __restrict__ buk,
                           const float* __restrict__ buv,  const float* __restrict__ buq,
                           const float* __restrict__ bqr) {
    int bid = blockIdx.x;
    int tx = threadIdx.x, ty = threadIdx.y;
    int tid = ty * 32 + tx;
    if (bid == 1888) {
        for (int k = tid; k < 2816; k += 256) {
            if (k < 512)
                g_bc1[k] = (k < 128) ? bdkv[k] : (k < 256) ? bdq[k-128] : bkr[k-256];
            g_bc2[k] = (k < 768) ? buk[k] : (k < 1792) ? buv[k-768]
                     : (k < 2560) ? buq[k-1792] : bqr[k-2560];
        }
        return;
    }
    const float* W; int ldn, Kdim, nB, dstN; __nv_bfloat16 *Oh, *Ol; int t;
    if (bid < 128)      { W=Wdkv; ldn=128;  Kdim=1024; nB=4;  Oh=g_W1h; Ol=g_W1l; dstN=0;    t=bid; }
    else if (bid < 256) { W=Wdq;  ldn=128;  Kdim=1024; nB=4;  Oh=g_W1h; Ol=g_W1l; dstN=128;  t=bid-128; }
    else if (bid < 512) { W=Wkr;  ldn=256;  Kdim=1024; nB=8;  Oh=g_W1h; Ol=g_W1l; dstN=256;  t=bid-256; }
    else if (bid < 608) { W=Wuk;  ldn=768;  Kdim=128;  nB=24; Oh=g_W2h; Ol=g_W2l; dstN=0;    t=bid-512; }
    else if (bid < 736) { W=Wuv;  ldn=1024; Kdim=128;  nB=32; Oh=g_W2h; Ol=g_W2l; dstN=768;  t=bid-608; }
    else if (bid < 832) { W=Wuq;  ldn=768;  Kdim=128;  nB=24; Oh=g_W2h; Ol=g_W2l; dstN=1792; t=bid-736; }
    else if (bid < 864) { W=Wqr;  ldn=256;  Kdim=128;  nB=8;  Oh=g_W2h; Ol=g_W2l; dstN=2560; t=bid-832; }
    else                { W=Wo;   ldn=1024; Kdim=1024; nB=32; Oh=g_Woh; Ol=g_Wol; dstN=0;    t=bid-864; }
    int n0 = (t % nB) * 32, k0 = (t / nB) * 32;
    const int P = Kdim >> 5;
    const int panel = k0 >> 5;

    __shared__ float tile[32][33];
#pragma unroll
    for (int j = 0; j < 32; j += 8)
        tile[ty + j][tx] = W[(size_t)(k0 + ty + j) * ldn + n0 + tx];
    __syncthreads();

#pragma unroll
    for (int half = 0; half < 2; half++) {
        int o = tid + half * 256;
        int word = o & 1, lane = (o >> 1) & 31, n8l = (o >> 6) & 3, j = o >> 8;
        int q4 = lane & 3;
        int n_rel = n8l * 8 + (lane >> 2);
        int k_rel = j * 16 + word * 8 + 2 * q4;
        float v0 = tile[k_rel][n_rel];
        float v1 = tile[k_rel + 1][n_rel];
        int n_glob = dstN + n0 + n_rel;
        size_t eo = ((size_t)(n_glob >> 7) * P + panel) * 4096
                  + (size_t)(j * 16 + ((n_glob & 127) >> 3)) * 128
                  + lane * 4 + word * 2;
        split_store(Oh, Ol, eo, v0, v1);
    }
}

// ---------------- shared GEMM pieces ----------------
#define AHo 0
#define ALo 8192
#define BHo 16384
#define BLo 24576
#define GSTAGE 32768
#define GSMEM_BYTES (2*GSTAGE)

// ---------------- bgemm_down ----------------
__global__ __launch_bounds__(256, 2)
void bgemm_down(const float* __restrict__ A, int lda,
                const __nv_bfloat16* __restrict__ Bh, const __nv_bfloat16* __restrict__ Bl,
                int Kdim, const float* __restrict__ bias,
                float* __restrict__ C, int ldc) {
    extern __shared__ char smraw[];
    const unsigned sm0 = smem_u32(smraw);

    const int tid  = threadIdx.x;
    const int lane = tid & 31;
    const int wid  = tid >> 5;
    const int rw   = wid & 3;
    const int cw   = wid >> 2;
    const int g    = lane >> 2;
    const int q4   = lane & 3;

    const int row0 = blockIdx.y * 128, col0 = blockIdx.x * 128;
    const int t4 = lane >> 2, w4 = lane & 3;
    const int P = Kdim >> 5;

    float acc[2][8][4];
#pragma unroll
    for (int mt = 0; mt < 2; mt++)
#pragma unroll
        for (int nt = 0; nt < 8; nt++)
#pragma unroll
            for (int c = 0; c < 4; c++) acc[mt][nt][c] = 0.0f;

    float4 aR[4];

    auto issue_B = [&](int buf, int p) {
        const unsigned stg = sm0 + buf * GSTAGE;
        size_t pb = ((size_t)blockIdx.x * P + p) * 4096;
        const __nv_bfloat16* sh = Bh + pb + tid * 8;
        const __nv_bfloat16* sl = Bl + pb + tid * 8;
        unsigned dh = stg + BHo + tid * 16;
        unsigned dl = stg + BLo + tid * 16;
        CP_ASYNC16(dh,        sh);
        CP_ASYNC16(dh + 4096, sh + 2048);
        CP_ASYNC16(dl,        sl);
        CP_ASYNC16(dl + 4096, sl + 2048);
        CP_COMMIT();
    };
    auto load_A = [&](int k0) {
#pragma unroll
        for (int p = 0; p < 4; p++) {
            int j = p & 1;
            int rloc = wid * 16 + ((p >> 1) << 3) + t4;
            const float* ap = A + (size_t)(row0 + rloc) * lda + k0 + j * 16 + 2 * w4;
            float2 x0 = *(const float2*)ap;
            float2 x1 = *(const float2*)(ap + 8);
            aR[p] = make_float4(x0.x, x0.y, x1.x, x1.y);
        }
    };
    auto store_A = [&](int buf) {
        const unsigned stg = sm0 + buf * GSTAGE;
#pragma unroll
        for (int p = 0; p < 4; p++) {
            int j = p & 1;
            int rloc = wid * 16 + ((p >> 1) << 3) + t4;
            __nv_bfloat162 h0 = __floats2bfloat162_rn(aR[p].x, aR[p].y);
            __nv_bfloat162 h1 = __floats2bfloat162_rn(aR[p].z, aR[p].w);
            __nv_bfloat162 l0 = __floats2bfloat162_rn(aR[p].x - __bfloat162float(h0.x),
                                                      aR[p].y - __bfloat162float(h0.y));
            __nv_bfloat162 l1 = __floats2bfloat162_rn(aR[p].z - __bfloat162float(h1.x),
                                                      aR[p].w - __bfloat162float(h1.y));
            int m16 = rloc >> 4, rh = (rloc >> 3) & 1;
            unsigned off = ((((j * 8 + m16) * 2 + rh) * 32) + ((rloc & 7) << 2) + w4) * 8;
            sts64(stg + AHo + off, bits2(h0), bits2(h1));
            sts64(stg + ALo + off, bits2(l0), bits2(l1));
        }
    };

    issue_B(0, 0);
    load_A(0);
    store_A(0);
    CP_WAIT0();
    __syncthreads();

    int cur = 0;
    for (int p = 0; p < P; p++) {
        bool has_next = (p + 1 < P);
        if (has_next) {
            issue_B(cur ^ 1, p + 1);
            load_A((p + 1) << 5);
        }

        const unsigned stg = sm0 + cur * GSTAGE;
#pragma unroll
        for (int j = 0; j < 2; j++) {
            unsigned ah[2][4], al[2][4];
#pragma unroll
            for (int mt = 0; mt < 2; mt++) {
                int m16 = rw * 2 + mt;
                unsigned abase = stg + ((((j * 8 + m16) * 2) * 32) + lane) * 8;
                uint2 u0 = lds64(abase + AHo);
                uint2 u1 = lds64(abase + AHo + 256);
                ah[mt][0] = u0.x; ah[mt][2] = u0.y; ah[mt][1] = u1.x; ah[mt][3] = u1.y;
                uint2 v0 = lds64(abase + ALo);
                uint2 v1 = lds64(abase + ALo + 256);
                al[mt][0] = v0.x; al[mt][2] = v0.y; al[mt][1] = v1.x; al[mt][3] = v1.y;
            }
#pragma unroll
            for (int nt = 0; nt < 8; nt++) {
                int n8 = cw * 8 + nt;
                unsigned bbase = stg + (((j * 16 + n8) * 32) + lane) * 8;
                uint2 bh = lds64(bbase + BHo);
                uint2 bl = lds64(bbase + BLo);
#pragma unroll
                for (int mt = 0; mt < 2; mt++) {
                    mma_bf16(acc[mt][nt], ah[mt], bh.x, bh.y);
                    mma_bf16(acc[mt][nt], ah[mt], bl.x, bl.y);
                    mma_bf16(acc[mt][nt], al[mt], bh.x, bh.y);
                }
            }
        }

        if (has_next) store_A(cur ^ 1);
        CP_WAIT0();
        __syncthreads();
        cur ^= 1;
    }

    // epilogue: cols<256 -> split images; fp32 always (cols<128 feed ckv_sum)
#pragma unroll
    for (int mt = 0; mt < 2; mt++)
#pragma unroll
        for (int i = 0; i < 2; i++) {
            int r = row0 + rw * 32 + mt * 16 + i * 8 + g;
#pragma unroll
            for (int nt = 0; nt < 8; nt++) {
                int c = col0 + cw * 64 + nt * 8 + 2 * q4;
                float x = acc[mt][nt][2 * i]     + bias[c];
                float y = acc[mt][nt][2 * i + 1] + bias[c + 1];
                if (c < 256) {
                    int k = c & 127;
                    __nv_bfloat16* ih = (c < 128) ? g_T1s1h : g_T1s2h;
                    __nv_bfloat16* il = (c < 128) ? g_T1s1l : g_T1s2l;
                    split_store(ih, il, frag_off(r, k, 4), x, y);
                }
                *(float2*)(C + (size_t)r * ldc + c) = make_float2(x, y);
            }
        }
}

// ---------------- bgemm_pp ----------------
__global__ __launch_bounds__(256, 2)
void bgemm_pp(const __nv_bfloat16* __restrict__ Ah, const __nv_bfloat16* __restrict__ Al,
              const __nv_bfloat16* __restrict__ Bh, const __nv_bfloat16* __restrict__ Bl,
              int Kdim, const float* __restrict__ bias,
              float* __restrict__ C, int ldc) {
    extern __shared__ char smraw[];
    const unsigned sm0 = smem_u32(smraw);

    const int tid  = threadIdx.x;
    const int lane = tid & 31;
    const int wid  = tid >> 5;
    const int rw   = wid & 3;
    const int cw   = wid >> 2;
    const int g    = lane >> 2;
    const int q4   = lane & 3;

    const int row0 = blockIdx.y * 128, col0 = blockIdx.x * 128;
    const int P = Kdim >> 5;

    float acc[2][8][4];
#pragma unroll
    for (int mt = 0; mt < 2; mt++)
#pragma unroll
        for (int nt = 0; nt < 8; nt++)
#pragma unroll
            for (int c = 0; c < 4; c++) acc[mt][nt][c] = 0.0f;

    auto issue = [&](int buf, int p) {
        const unsigned stg = sm0 + buf * GSTAGE;
        size_t pa = ((size_t)blockIdx.y * P + p) * 4096;
        size_t pb = ((size_t)blockIdx.x * P + p) * 4096;
        unsigned da = stg + AHo + tid * 16;
        unsigned db = stg + BHo + tid * 16;
        CP_ASYNC16(da,                Ah + pa + tid * 8);
        CP_ASYNC16(da + 4096,         Ah + pa + 2048 + tid * 8);
        CP_ASYNC16(da + (ALo-AHo),        Al + pa + tid * 8);
        CP_ASYNC16(da + (ALo-AHo) + 4096, Al + pa + 2048 + tid * 8);
        CP_ASYNC16(db,                Bh + pb + tid * 8);
        CP_ASYNC16(db + 4096,         Bh + pb + 2048 + tid * 8);
        CP_ASYNC16(db + (BLo-BHo),        Bl + pb + tid * 8);
        CP_ASYNC16(db + (BLo-BHo) + 4096, Bl + pb + 2048 + tid * 8);
        CP_COMMIT();
    };

    issue(0, 0);
    CP_WAIT0();
    __syncthreads();

    int cur = 0;
    for (int p = 0; p < P; p++) {
        bool has_next = (p + 1 < P);
        if (has_next) issue(cur ^ 1, p + 1);

        const unsigned stg = sm0 + cur * GSTAGE;
#pragma unroll
        for (int j = 0; j < 2; j++) {
            unsigned ah[2][4], al[2][4];
#pragma unroll
            for (int mt = 0; mt < 2; mt++) {
                int m16 = rw * 2 + mt;
                unsigned abase = stg + ((((j * 8 + m16) * 2) * 32) + lane) * 8;
                uint2 u0 = lds64(abase + AHo);
                uint2 u1 = lds64(abase + AHo + 256);
                ah[mt][0] = u0.x; ah[mt][2] = u0.y; ah[mt][1] = u1.x; ah[mt][3] = u1.y;
                uint2 v0 = lds64(abase + ALo);
                uint2 v1 = lds64(abase + ALo + 256);
                al[mt][0] = v0.x; al[mt][2] = v0.y; al[mt][1] = v1.x; al[mt][3] = v1.y;
            }
#pragma unroll
            for (int nt = 0; nt < 8; nt++) {
                int n8 = cw * 8 + nt;
                unsigned bbase = stg + (((j * 16 + n8) * 32) + lane) * 8;
                uint2 bh = lds64(bbase + BHo);
                uint2 bl = lds64(bbase + BLo);
#pragma unroll
                for (int mt = 0; mt < 2; mt++) {
                    mma_bf16(acc[mt][nt], ah[mt], bh.x, bh.y);
                    mma_bf16(acc[mt][nt], ah[mt], bl.x, bl.y);
                    mma_bf16(acc[mt][nt], al[mt], bh.x, bh.y);
                }
            }
        }

        CP_WAIT0();
        __syncthreads();
        cur ^= 1;
    }

#pragma unroll
    for (int mt = 0; mt < 2; mt++)
#pragma unroll
        for (int i = 0; i < 2; i++) {
            int r = row0 + rw * 32 + mt * 16 + i * 8 + g;
#pragma unroll
            for (int nt = 0; nt < 8; nt++) {
                int c = col0 + cw * 64 + nt * 8 + 2 * q4;
                float2 o2;
                o2.x = acc[mt][nt][2 * i]     + bias[c];
                o2.y = acc[mt][nt][2 * i + 1] + bias[c + 1];
                *(float2*)(C + (size_t)r * ldc + c) = o2;
            }
        }
}

// ---------------- Vsum path (more parallel): sum_s c_kv, then @ W_uv ----------------
__global__ void ckv_sum(const float* __restrict__ T1) {   // grid (32, 2), 256 thr
    __shared__ float part[2][128];
    int seg = blockIdx.x, b = blockIdx.y;
    int c = threadIdx.x & 127, p = threadIdx.x >> 7;      // 2 halves of 32 rows
    const float* base = T1 + ((size_t)(b * 2048 + seg * 64 + p * 32)) * 512 + c;
    float s = 0.0f;
#pragma unroll 8
    for (int r = 0; r < 32; r++) s += base[(size_t)r * 512];
    part[p][c] = s;
    __syncthreads();
    if (p == 0)
        g_part[(b * 32 + seg) * 128 + c] = part[0][c] + part[1][c];
}

__global__ void vsum_k(const float* __restrict__ Wuv, const float* __restrict__ buv) {
    // grid (8, 2), 512 thr; 4-way split of the c loop per output column
    __shared__ float cs[128];
    __shared__ float red[4][128];
    int blk = blockIdx.x, b = blockIdx.y;
    int nl = threadIdx.x & 127, cp = threadIdx.x >> 7;    // 0..3
    if (threadIdx.x < 128) {
        float s = 0.0f;
#pragma unroll
        for (int ph = 0; ph < 32; ph++) s += g_part[(b * 32 + ph) * 128 + threadIdx.x];
        cs[threadIdx.x] = s;
    }
    __syncthreads();
    int n = blk * 128 + nl;
    float s = 0.0f;
#pragma unroll 8
    for (int c = cp * 32; c < cp * 32 + 32; c++) s += cs[c] * Wuv[c * 1024 + n];
    red[cp][nl] = s;
    __syncthreads();
    if (cp == 0)
        g_Vsum[b * 1024 + n] = 2048.0f * buv[n]
            + ((red[0][nl] + red[1][nl]) + (red[2][nl] + red[3][nl]));
}

// ---------------- rope + layout assemble: paired bf16 stores for Q,K ----------------
__global__ void assemble_qkv(const float* __restrict__ T1, const float* __restrict__ T2) {
    int row = blockIdx.x;
    int b = row >> 11, pos = row & 2047;
    float t = (float)pos * (1.0f / 40.0f);
    const float* t2row = T2 + (size_t)row * 2816;
    const float* t1row = T1 + (size_t)row * 512;
    const int kt = pos >> 6, rk = pos & 63;
    const int qt = pos >> 7, rq = pos & 127;
#pragma unroll
    for (int it = 0; it < 2; it++) {
        int pi = threadIdx.x + (it << 8);      // pair index 0..511
        int h = pi >> 5, dp = (pi & 31) * 2;   // d = dp, dp+1 (same region: boundaries even)
        int bh = b * Hh + h;
        size_t ktile = ((size_t)bh * 32 + kt) * 4096;
        // V bf16 B-image (n=d, k=rk) — pairs not adjacent, two scalar stores
        g_Vb[ktile + bfrag_off(dp,     rk)] = __float2bfloat16(t2row[768 + h*64 + dp]);
        g_Vb[ktile + bfrag_off(dp + 1, rk)] = __float2bfloat16(t2row[768 + h*64 + dp + 1]);
        float qv0, kv0, qv1, kv1;
        if (dp < 48) {
            qv0 = t2row[1792 + h*48 + dp];     qv1 = t2row[1792 + h*48 + dp + 1];
            kv0 = t2row[h*48 + dp];            kv1 = t2row[h*48 + dp + 1];
        } else {
            int j = dp - 48;                   // even; pair (j, j+1) in same sub-region
            const float* xq = t2row + 2560 + h*16;
            const float* xk = t1row + 256  + h*16;
            if (j >= 8) { qv0 = xq[j]; kv0 = xk[j]; qv1 = xq[j+1]; kv1 = xk[j+1]; }
            else {
                int jj0 = j & 3, jj1 = (j + 1) & 3;
                float a0 = t * powf(10000.0f, -0.25f * (float)jj0);
                float a1 = t * powf(10000.0f, -0.25f * (float)jj1);
                float sn0, cs0, sn1, cs1;
                sincosf(a0, &sn0, &cs0);
                sincosf(a1, &sn1, &cs1);
                if (j < 4) {
                    qv0 = xq[j]*cs0 - xq[j+4]*sn0;   kv0 = xk[j]*cs0 - xk[j+4]*sn0;
                    qv1 = xq[j+1]*cs1 - xq[j+5]*sn1; kv1 = xk[j+1]*cs1 - xk[j+5]*sn1;
                } else {
                    qv0 = xq[j]*cs0 + xq[j-4]*sn0;   kv0 = xk[j]*cs0 + xk[j-4]*sn0;
                    qv1 = xq[j+1]*cs1 + xq[j-3]*sn1; kv1 = xk[j+1]*cs1 + xk[j-3]*sn1;
                }
            }
        }
        // Q bf16 A-image: (dp, dp+1) adjacent -> one bf16x2 store
        size_t qoff = ((size_t)bh * 16 + qt) * 8192 + frag_off(rq, dp, 2);
        *(__nv_bfloat162*)(g_Qb + qoff) = __floats2bfloat162_rn(qv0 * 0.125f, qv1 * 0.125f);
        // K bf16 B-image: (k=dp, dp+1) adjacent -> one bf16x2 store
        size_t koff = ktile + bfrag_off(rk, dp);
        *(__nv_bfloat162*)(g_Kb + koff) = __floats2bfloat162_rn(kv0, kv1);
    }
}

// ---------------- flash attention v6: subtract-1 softmax, bf16 k16, cp.async ----------------
// smem: QF[0,16384) KF[16384,24576) VF[24576,32768) PS[32768,49152) RED[49152,50176)
#define QF_OFF   0
#define KF_OFF   16384
#define VF_OFF   24576
#define PS_OFF   32768
#define RED_OFF  49152
#define FLASH_SMEM 50176

__global__ __launch_bounds__(256, 2)
void flash_bf16(const __nv_bfloat16* __restrict__ Qb, const __nv_bfloat16* __restrict__ Kb,
                const __nv_bfloat16* __restrict__ Vb) {
    extern __shared__ char smraw[];
    const unsigned sm0 = smem_u32(smraw);
    const unsigned QF = sm0 + QF_OFF, KF = sm0 + KF_OFF;
    const unsigned VF = sm0 + VF_OFF, PSb = sm0 + PS_OFF;
    float* Red = (float*)(smraw + RED_OFF);

    const int tid  = threadIdx.x;
    const int lane = tid & 31;
    const int w    = tid >> 5;
    const int rw   = w & 3;
    const int cw   = w >> 2;
    const int g    = lane >> 2;
    const int q4   = lane & 3;

    const int qb = blockIdx.x, h = blockIdx.y, b = blockIdx.z;
    const int bh = b * Hh + h;
    const __nv_bfloat16* Qimg = Qb + ((size_t)bh * 16 + qb) * 8192;
    const __nv_bfloat16* Kimg = Kb + (size_t)bh * 32 * 4096;
    const __nv_bfloat16* Vimg = Vb + (size_t)bh * 32 * 4096;

    auto issueK = [&](int t) {
        const __nv_bfloat16* src = Kimg + (size_t)t * 4096 + tid * 8;
        unsigned dst = KF + tid * 16;
        CP_ASYNC16(dst,        src);
        CP_ASYNC16(dst + 4096, src + 2048);
        CP_COMMIT();
    };
    auto issueV = [&](int t) {
        const __nv_bfloat16* src = Vimg + (size_t)t * 4096 + tid * 8;
        unsigned dst = VF + tid * 16;
        CP_ASYNC16(dst,        src);
        CP_ASYNC16(dst + 4096, src + 2048);
        CP_COMMIT();
    };

    // prologue: Q (once) + first K/V tile
    {
        const __nv_bfloat16* src = Qimg + tid * 8;
        unsigned dst = QF + tid * 16;
        CP_ASYNC16(dst,         src);
        CP_ASYNC16(dst + 4096,  src + 2048);
        CP_ASYNC16(dst + 8192,  src + 4096);
        CP_ASYNC16(dst + 12288, src + 6144);
        CP_COMMIT();
    }
    issueK(0);
    issueV(0);
    CP_WAIT0();
    __syncthreads();

    float lsum[2][2], o[2][4][4];
#pragma unroll
    for (int mt = 0; mt < 2; mt++)
#pragma unroll
        for (int i = 0; i < 2; i++) lsum[mt][i] = 0.0f;
#pragma unroll
    for (int mt = 0; mt < 2; mt++)
#pragma unroll
        for (int nt = 0; nt < 4; nt++)
#pragma unroll
            for (int c = 0; c < 4; c++) o[mt][nt][c] = 0.0f;

    for (int kt = 0; kt < 32; kt++) {
        // ---- S = Q @ K^T ----
        float sfr[2][4][4];
#pragma unroll
        for (int mt = 0; mt < 2; mt++)
#pragma unroll
            for (int nt = 0; nt < 4; nt++)
#pragma unroll
                for (int c = 0; c < 4; c++) sfr[mt][nt][c] = 0.0f;

#pragma unroll
        for (int s = 0; s < 4; s++) {
            int p = s >> 1, j = s & 1;
            unsigned af[2][4];
#pragma unroll
            for (int mt = 0; mt < 2; mt++) {
                unsigned ab = QF + p * 8192
                            + (unsigned)((j * 8 + rw * 2 + mt) * 2) * 256 + (lane << 3);
                uint2 u0 = lds64(ab);
                uint2 u1 = lds64(ab + 256);
                af[mt][0] = u0.x; af[mt][1] = u1.x; af[mt][2] = u0.y; af[mt][3] = u1.y;
            }
#pragma unroll
            for (int nt = 0; nt < 4; nt++) {
                uint2 bf = lds64(KF + p * 4096
                                 + (unsigned)(j * 8 + cw * 4 + nt) * 256 + (lane << 3));
#pragma unroll
                for (int mt = 0; mt < 2; mt++)
                    mma_bf16(sfr[mt][nt], af[mt], bf.x, bf.y);
            }
        }

        // ---- p' = exp(s)-1 (subtract-1 trick), write bf16 P' image, local sums ----
#pragma unroll
        for (int mt = 0; mt < 2; mt++)
#pragma unroll
            for (int i = 0; i < 2; i++) {
#pragma unroll
                for (int jj = 0; jj < 2; jj++) {
                    float p0 = __expf(sfr[mt][2*jj][2*i])     - 1.0f;
                    float p1 = __expf(sfr[mt][2*jj][2*i+1])   - 1.0f;
                    float p2 = __expf(sfr[mt][2*jj+1][2*i])   - 1.0f;
                    float p3 = __expf(sfr[mt][2*jj+1][2*i+1]) - 1.0f;
                    lsum[mt][i] += (p0 + p1) + (p2 + p3);
                    unsigned addr = PSb + cw * 8192
                                  + (unsigned)((jj * 8 + rw * 2 + mt) * 2 + i) * 256
                                  + ((unsigned)(g * 4 + q4) << 3);
                    sts64(addr, bits2(__floats2bfloat162_rn(p0, p1)),
                                bits2(__floats2bfloat162_rn(p2, p3)));
                }
            }

        CP_WAIT0();          // V(kt) landed
        __syncthreads();     // PS visible; KF free; VF visible
        if (kt + 1 < 32) issueK(kt + 1);

        // ---- O += P' @ V ----
#pragma unroll
        for (int s = 0; s < 4; s++) {
            int p = s >> 1, j = s & 1;
            unsigned pa[2][4];
#pragma unroll
            for (int mt = 0; mt < 2; mt++) {
                unsigned ab = PSb + p * 8192
                            + (unsigned)((j * 8 + rw * 2 + mt) * 2) * 256 + (lane << 3);
                uint2 u0 = lds64(ab);
                uint2 u1 = lds64(ab + 256);
                pa[mt][0] = u0.x; pa[mt][1] = u1.x; pa[mt][2] = u0.y; pa[mt][3] = u1.y;
            }
#pragma unroll
            for (int nt = 0; nt < 4; nt++) {
                uint2 vb = lds64(VF + (unsigned)p * 4096
                                 + (unsigned)(j * 8 + cw * 4 + nt) * 256 + (lane << 3));
#pragma unroll
                for (int mt = 0; mt < 2; mt++)
                    mma_bf16(o[mt][nt], pa[mt], vb.x, vb.y);
            }
        }

        __syncthreads();     // VF free, PS free
        if (kt + 1 < 32) {
            issueV(kt + 1);
            CP_WAIT1();      // K(kt+1) landed (V may still fly)
            __syncthreads(); // KF visible
        }
    }

    // ---- final denominator: l = 2048 + sum p' ----
#pragma unroll
    for (int mt = 0; mt < 2; mt++)
#pragma unroll
        for (int i = 0; i < 2; i++) {
            float s = lsum[mt][i];
            s += __shfl_xor_sync(0xffffffffu, s, 1);
            s += __shfl_xor_sync(0xffffffffu, s, 2);
            if (q4 == 0) Red[(rw*32 + mt*16 + i*8 + g)*2 + cw] = s;
        }
    __syncthreads();

    // ---- epilogue: o = (Vsum + P'V) / l, write split frag-ordered O images ----
#pragma unroll
    for (int mt = 0; mt < 2; mt++)
#pragma unroll
        for (int i = 0; i < 2; i++) {
            int rloc = rw*32 + mt*16 + i*8 + g;
            int r = b*Sq + qb*128 + rloc;
            float l = 2048.0f + Red[rloc*2] + Red[rloc*2 + 1];
            float inv = 1.0f / l;
#pragma unroll
            for (int nt = 0; nt < 4; nt++) {
                int col = cw*32 + nt*8 + 2*q4;
                float vs0 = g_Vsum[b*1024 + h*64 + col];
                float vs1 = g_Vsum[b*1024 + h*64 + col + 1];
                int k = h*64 + col;
                split_store(g_Osh, g_Osl, frag_off(r, k, 32),
                            (o[mt][nt][2*i]   + vs0) * inv,
                            (o[mt][nt][2*i+1] + vs1) * inv);
            }
        }
}

// ---------------- launch ----------------
extern "C" void kernel_launch(void* const* d_in, const int* in_sizes, int n_in,
                              void* d_out, int out_size) {
    (void)in_sizes; (void)n_in; (void)out_size;
    const float* h    = (const float*)d_in[0];
    const float* Wdkv = (const float*)d_in[1];
    const float* bdkv = (const float*)d_in[2];
    const float* Wdq  = (const float*)d_in[3];
    const float* bdq  = (const float*)d_in[4];
    const float* Wuk  = (const float*)d_in[5];
    const float* buk  = (const float*)d_in[6];
    const float* Wuv  = (const float*)d_in[7];
    const float* buv  = (const float*)d_in[8];
    const float* Wuq  = (const float*)d_in[9];
    const float* buq  = (const float*)d_in[10];
    const float* Wqr  = (const float*)d_in[11];
    const float* bqr  = (const float*)d_in[12];
    const float* Wkr  = (const float*)d_in[13];
    const float* bkr  = (const float*)d_in[14];
    const float* Wo   = (const float*)d_in[15];
    const float* bo   = (const float*)d_in[16];
    float* out = (float*)d_out;

    float *T1, *T2, *bc1, *bc2;
    __nv_bfloat16 *W1h, *W1l, *W2h, *W2l, *Woh, *Wol;
    __nv_bfloat16 *T1s1h, *T1s1l, *T1s2h, *T1s2l, *Osh, *Osl;
    __nv_bfloat16 *Qb, *Kb, *Vb;
    cudaGetSymbolAddress((void**)&T1,  g_T1);
    cudaGetSymbolAddress((void**)&T2,  g_T2);
    cudaGetSymbolAddress((void**)&bc1, g_bc1);
    cudaGetSymbolAddress((void**)&bc2, g_bc2);
    cudaGetSymbolAddress((void**)&W1h, g_W1h);
    cudaGetSymbolAddress((void**)&W1l, g_W1l);
    cudaGetSymbolAddress((void**)&W2h, g_W2h);
    cudaGetSymbolAddress((void**)&W2l, g_W2l);
    cudaGetSymbolAddress((void**)&Woh, g_Woh);
    cudaGetSymbolAddress((void**)&Wol, g_Wol);
    cudaGetSymbolAddress((void**)&T1s1h, g_T1s1h);
    cudaGetSymbolAddress((void**)&T1s1l, g_T1s1l);
    cudaGetSymbolAddress((void**)&T1s2h, g_T1s2h);
    cudaGetSymbolAddress((void**)&T1s2l, g_T1s2l);
    cudaGetSymbolAddress((void**)&Osh, g_Osh);
    cudaGetSymbolAddress((void**)&Osl, g_Osl);
    cudaGetSymbolAddress((void**)&Qb,  g_Qb);
    cudaGetSymbolAddress((void**)&Kb,  g_Kb);
    cudaGetSymbolAddress((void**)&Vb,  g_Vb);

    static int attr_set = 0;
    if (!attr_set) {
        cudaFuncSetAttribute(flash_bf16, cudaFuncAttributeMaxDynamicSharedMemorySize,
                             FLASH_SMEM);
        cudaFuncSetAttribute(bgemm_down, cudaFuncAttributeMaxDynamicSharedMemorySize,
                             GSMEM_BYTES);
        cudaFuncSetAttribute(bgemm_pp, cudaFuncAttributeMaxDynamicSharedMemorySize,
                             GSMEM_BYTES);
        attr_set = 1;
    }

    // 1) weight transpose + bf16 split (fragment-ordered) + bias pack
    wsplit_all<<<1889, dim3(32, 8)>>>(Wdkv, Wdq, Wkr, Wuk, Wuv, Wuq, Wqr, Wo,
                                      bdkv, bdq, bkr, buk, buv, buq, bqr);

    // 2) down-proj + k_rot raw
    bgemm_down<<<dim3(4, 32), 256, GSMEM_BYTES>>>(h, Dm, W1h, W1l, 1024, bc1, T1, 512);

    // 2b) Vsum path (parallel): sum_s c_kv, then mini-gemm with W_uv
    ckv_sum<<<dim3(32, 2), 256>>>(T1);
    vsum_k<<<dim3(8, 2), 512>>>(Wuv, buv);

    // 3) up-projections (K=128)
    bgemm_pp<<<dim3(14, 32), 256, GSMEM_BYTES>>>(T1s1h, T1s1l, W2h, W2l, 128, bc2, T2, 2816);
    bgemm_pp<<<dim3(8, 32), 256, GSMEM_BYTES>>>(T1s2h, T1s2l,
                                                W2h + (size_t)14*4*4096, W2l + (size_t)14*4*4096,
                                                128, bc2 + 1792, T2 + 1792, 2816);

    // 4) rope + layout (bf16 frag images, paired Q/K stores)
    assemble_qkv<<<BS, 256>>>(T1, T2);

    // 5) attention (subtract-1 softmax, bf16 k16, cp.async)
    flash_bf16<<<dim3(Sq/128, Hh, Bsz), 256, FLASH_SMEM>>>(Qb, Kb, Vb);

    // 6) output projection
    bgemm_pp<<<dim3(8, 32), 256, GSMEM_BYTES>>>(Osh, Osl, Woh, Wol, 1024, bo, out, 1024);
}

// round 16
// speedup vs baseline: 1.0122x; 1.0122x over previous
#include <cuda_runtime.h>
#include <cuda_bf16.h>
#include <math.h>
#include <stdint.h>

// Problem dims
#define Bsz 2
#define Sq  2048
#define Dm  1024
#define Hh  16
#define DHd 64
#define DRr 16
#define SDd 48
#define DCc 128
#define BS  (Bsz*Sq)   // 4096

// ---------------- device scratch (no allocs allowed) ----------------
__device__ float g_T1[(size_t)BS*512];
__device__ float g_T2[(size_t)BS*2816];
__device__ float g_bc1[512];
__device__ float g_bc2[2816];
__device__ float g_part[2*32*128];
__device__ float g_Vsum[2*1024];
// bf16-split weights, FRAGMENT-ORDERED: [colblock][panel][4096 elems]
__device__ __nv_bfloat16 g_W1h[512*1024],  g_W1l[512*1024];    // 4 cb x 32 p
__device__ __nv_bfloat16 g_W2h[2816*128],  g_W2l[2816*128];    // 22 cb x 4 p
__device__ __nv_bfloat16 g_Woh[1024*1024], g_Wol[1024*1024];   // 8 cb x 32 p
// bf16-split ACTIVATION images (A-operands), fragment-ordered [rowblock][panel][4096]
__device__ __nv_bfloat16 g_T1s1h[(size_t)BS*128], g_T1s1l[(size_t)BS*128];  // c_kv
__device__ __nv_bfloat16 g_T1s2h[(size_t)BS*128], g_T1s2l[(size_t)BS*128];  // c_q
__device__ __nv_bfloat16 g_Osh[(size_t)BS*1024],  g_Osl[(size_t)BS*1024];   // attn out
// bf16 attention operand images
__device__ __nv_bfloat16 g_Qb[(size_t)Bsz*Hh*Sq*64];   // A-images per (b,h,qtile): 2 panels x 4096
__device__ __nv_bfloat16 g_Kb[(size_t)Bsz*Hh*Sq*64];   // B-images per (b,h,ktile): 4096 elems
__device__ __nv_bfloat16 g_Vb[(size_t)Bsz*Hh*Sq*64];   // V bf16 B-images

// ---------------- helpers ----------------
__device__ __forceinline__ void mma_bf16(float c[4], const unsigned a[4],
                                         unsigned b0, unsigned b1) {
    asm volatile(
        "mma.sync.aligned.m16n8k16.row.col.f32.bf16.bf16.f32 "
        "{%0,%1,%2,%3}, {%4,%5,%6,%7}, {%8,%9}, {%0,%1,%2,%3};"
        : "+f"(c[0]), "+f"(c[1]), "+f"(c[2]), "+f"(c[3])
        : "r"(a[0]), "r"(a[1]), "r"(a[2]), "r"(a[3]), "r"(b0), "r"(b1));
}
__device__ __forceinline__ unsigned smem_u32(const void* p) {
    unsigned a;
    asm("{ .reg .u64 t; cvta.to.shared.u64 t, %1; cvt.u32.u64 %0, t; }" : "=r"(a) : "l"(p));
    return a;
}
__device__ __forceinline__ void sts64(unsigned addr, unsigned a, unsigned b) {
    asm volatile("st.shared.v2.b32 [%0], {%1,%2};" :: "r"(addr), "r"(a), "r"(b));
}
__device__ __forceinline__ uint2 lds64(unsigned addr) {
    uint2 v;
    asm volatile("ld.shared.v2.b32 {%0,%1}, [%2];" : "=r"(v.x), "=r"(v.y) : "r"(addr));
    return v;
}
__device__ __forceinline__ unsigned bits2(__nv_bfloat162 v) {
    return *reinterpret_cast<unsigned*>(&v);
}
#define CP_ASYNC16(sm, gp) \
    asm volatile("cp.async.cg.shared.global [%0], [%1], 16;" :: "r"(sm), "l"(gp) : "memory")
#define CP_COMMIT() asm volatile("cp.async.commit_group;" ::: "memory")
#define CP_WAIT0()  asm volatile("cp.async.wait_group 0;" ::: "memory")

__device__ __forceinline__ void split_store(__nv_bfloat16* ih, __nv_bfloat16* il,
                                            size_t eo, float x, float y) {
    __nv_bfloat162 hp = __floats2bfloat162_rn(x, y);
    float h0 = __bfloat162float(__low2bfloat16(hp));
    float h1 = __bfloat162float(__high2bfloat16(hp));
    __nv_bfloat162 lp = __floats2bfloat162_rn(x - h0, y - h1);
    *(__nv_bfloat162*)(ih + eo) = hp;
    *(__nv_bfloat162*)(il + eo) = lp;
}

// element offset of (r,k) in a frag-ordered A image with P k-panels (k even)
__device__ __forceinline__ size_t frag_off(int r, int k, int P) {
    return ((size_t)(r >> 7) * P + (k >> 5)) * 4096
         + (size_t)(((((k >> 4) & 1) * 8 + ((r >> 4) & 7)) * 2 + ((r >> 3) & 1)) * 128)
         + (size_t)(((r & 7) * 4 + ((k >> 1) & 3)) * 4) + (size_t)(((k >> 3) & 1) * 2);
}
// element offset of (n,k) in a 64-col B frag image (per-tile 4096 elems)
__device__ __forceinline__ size_t bfrag_off(int n, int k) {
    return (size_t)((k >> 5) * 2048)
         + (size_t)((((k >> 4) & 1) * 8 + (n >> 3)) * 128)
         + (size_t)(((n & 7) * 4 + ((k >> 1) & 3)) * 4)
         + (size_t)(((k >> 3) & 1) * 2) + (size_t)(k & 1);
}

// ---------------- merged weight transpose/split -> fragment-ordered gmem ----------------
__global__ void wsplit_all(const float* __restrict__ Wdkv, const float* __restrict__ Wdq,
                           const float* __restrict__ Wkr,  const float* __restrict__ Wuk,
                           const float* __restrict__ Wuv,  const float* __restrict__ Wuq,
                           const float* __restrict__ Wqr,  const float* __restrict__ Wo,
                           const float* __restrict__ bdkv, const float* __restrict__ bdq,
                           const float* __restrict__ bkr,  const float* __restrict__ buk,
                           const float* __restrict__ buv,  const float* __restrict__ buq,
                           const float* __restrict__ bqr) {
    int bid = blockIdx.x;
    int tx = threadIdx.x, ty = threadIdx.y;
    int tid = ty * 32 + tx;
    if (bid == 1888) {
        for (int k = tid; k < 2816; k += 256) {
            if (k < 512)
                g_bc1[k] = (k < 128) ? bdkv[k] : (k < 256) ? bdq[k-128] : bkr[k-256];
            g_bc2[k] = (k < 768) ? buk[k] : (k < 1792) ? buv[k-768]
                     : (k < 2560) ? buq[k-1792] : bqr[k-2560];
        }
        return;
    }
    const float* W; int ldn, Kdim, nB, dstN; __nv_bfloat16 *Oh, *Ol; int t;
    if (bid < 128)      { W=Wdkv; ldn=128;  Kdim=1024; nB=4;  Oh=g_W1h; Ol=g_W1l; dstN=0;    t=bid; }
    else if (bid < 256) { W=Wdq;  ldn=128;  Kdim=1024; nB=4;  Oh=g_W1h; Ol=g_W1l; dstN=128;  t=bid-128; }
    else if (bid < 512) { W=Wkr;  ldn=256;  Kdim=1024; nB=8;  Oh=g_W1h; Ol=g_W1l; dstN=256;  t=bid-256; }
    else if (bid < 608) { W=Wuk;  ldn=768;  Kdim=128;  nB=24; Oh=g_W2h; Ol=g_W2l; dstN=0;    t=bid-512; }
    else if (bid < 736) { W=Wuv;  ldn=1024; Kdim=128;  nB=32; Oh=g_W2h; Ol=g_W2l; dstN=768;  t=bid-608; }
    else if (bid < 832) { W=Wuq;  ldn=768;  Kdim=128;  nB=24; Oh=g_W2h; Ol=g_W2l; dstN=1792; t=bid-736; }
    else if (bid < 864) { W=Wqr;  ldn=256;  Kdim=128;  nB=8;  Oh=g_W2h; Ol=g_W2l; dstN=2560; t=bid-832; }
    else                { W=Wo;   ldn=1024; Kdim=1024; nB=32; Oh=g_Woh; Ol=g_Wol; dstN=0;    t=bid-864; }
    int n0 = (t % nB) * 32, k0 = (t / nB) * 32;
    const int P = Kdim >> 5;
    const int panel = k0 >> 5;

    __shared__ float tile[32][33];
#pragma unroll
    for (int j = 0; j < 32; j += 8)
        tile[ty + j][tx] = W[(size_t)(k0 + ty + j) * ldn + n0 + tx];
    __syncthreads();

#pragma unroll
    for (int half = 0; half < 2; half++) {
        int o = tid + half * 256;
        int word = o & 1, lane = (o >> 1) & 31, n8l = (o >> 6) & 3, j = o >> 8;
        int q4 = lane & 3;
        int n_rel = n8l * 8 + (lane >> 2);
        int k_rel = j * 16 + word * 8 + 2 * q4;
        float v0 = tile[k_rel][n_rel];
        float v1 = tile[k_rel + 1][n_rel];
        int n_glob = dstN + n0 + n_rel;
        size_t eo = ((size_t)(n_glob >> 7) * P + panel) * 4096
                  + (size_t)(j * 16 + ((n_glob & 127) >> 3)) * 128
                  + lane * 4 + word * 2;
        split_store(Oh, Ol, eo, v0, v1);
    }
}

// ---------------- shared GEMM pieces ----------------
#define AHo 0
#define ALo 8192
#define BHo 16384
#define BLo 24576
#define GSTAGE 32768
#define GSMEM_BYTES (2*GSTAGE)

// ---------------- bgemm_down ----------------
__global__ __launch_bounds__(256, 2)
void bgemm_down(const float* __restrict__ A, int lda,
                const __nv_bfloat16* __restrict__ Bh, const __nv_bfloat16* __restrict__ Bl,
                int Kdim, const float* __restrict__ bias,
                float* __restrict__ C, int ldc) {
    extern __shared__ char smraw[];
    const unsigned sm0 = smem_u32(smraw);

    const int tid  = threadIdx.x;
    const int lane = tid & 31;
    const int wid  = tid >> 5;
    const int rw   = wid & 3;
    const int cw   = wid >> 2;
    const int g    = lane >> 2;
    const int q4   = lane & 3;

    const int row0 = blockIdx.y * 128, col0 = blockIdx.x * 128;
    const int t4 = lane >> 2, w4 = lane & 3;
    const int P = Kdim >> 5;

    float acc[2][8][4];
#pragma unroll
    for (int mt = 0; mt < 2; mt++)
#pragma unroll
        for (int nt = 0; nt < 8; nt++)
#pragma unroll
            for (int c = 0; c < 4; c++) acc[mt][nt][c] = 0.0f;

    float4 aR[4];

    auto issue_B = [&](int buf, int p) {
        const unsigned stg = sm0 + buf * GSTAGE;
        size_t pb = ((size_t)blockIdx.x * P + p) * 4096;
        const __nv_bfloat16* sh = Bh + pb + tid * 8;
        const __nv_bfloat16* sl = Bl + pb + tid * 8;
        unsigned dh = stg + BHo + tid * 16;
        unsigned dl = stg + BLo + tid * 16;
        CP_ASYNC16(dh,        sh);
        CP_ASYNC16(dh + 4096, sh + 2048);
        CP_ASYNC16(dl,        sl);
        CP_ASYNC16(dl + 4096, sl + 2048);
        CP_COMMIT();
    };
    auto load_A = [&](int k0) {
#pragma unroll
        for (int p = 0; p < 4; p++) {
            int j = p & 1;
            int rloc = wid * 16 + ((p >> 1) << 3) + t4;
            const float* ap = A + (size_t)(row0 + rloc) * lda + k0 + j * 16 + 2 * w4;
            float2 x0 = *(const float2*)ap;
            float2 x1 = *(const float2*)(ap + 8);
            aR[p] = make_float4(x0.x, x0.y, x1.x, x1.y);
        }
    };
    auto store_A = [&](int buf) {
        const unsigned stg = sm0 + buf * GSTAGE;
#pragma unroll
        for (int p = 0; p < 4; p++) {
            int j = p & 1;
            int rloc = wid * 16 + ((p >> 1) << 3) + t4;
            __nv_bfloat162 h0 = __floats2bfloat162_rn(aR[p].x, aR[p].y);
            __nv_bfloat162 h1 = __floats2bfloat162_rn(aR[p].z, aR[p].w);
            __nv_bfloat162 l0 = __floats2bfloat162_rn(aR[p].x - __bfloat162float(h0.x),
                                                      aR[p].y - __bfloat162float(h0.y));
            __nv_bfloat162 l1 = __floats2bfloat162_rn(aR[p].z - __bfloat162float(h1.x),
                                                      aR[p].w - __bfloat162float(h1.y));
            int m16 = rloc >> 4, rh = (rloc >> 3) & 1;
            unsigned off = ((((j * 8 + m16) * 2 + rh) * 32) + ((rloc & 7) << 2) + w4) * 8;
            sts64(stg + AHo + off, bits2(h0), bits2(h1));
            sts64(stg + ALo + off, bits2(l0), bits2(l1));
        }
    };

    issue_B(0, 0);
    load_A(0);
    store_A(0);
    CP_WAIT0();
    __syncthreads();

    int cur = 0;
    for (int p = 0; p < P; p++) {
        bool has_next = (p + 1 < P);
        if (has_next) {
            issue_B(cur ^ 1, p + 1);
            load_A((p + 1) << 5);
        }

        const unsigned stg = sm0 + cur * GSTAGE;
#pragma unroll
        for (int j = 0; j < 2; j++) {
            unsigned ah[2][4], al[2][4];
#pragma unroll
            for (int mt = 0; mt < 2; mt++) {
                int m16 = rw * 2 + mt;
                unsigned abase = stg + ((((j * 8 + m16) * 2) * 32) + lane) * 8;
                uint2 u0 = lds64(abase + AHo);
                uint2 u1 = lds64(abase + AHo + 256);
                ah[mt][0] = u0.x; ah[mt][2] = u0.y; ah[mt][1] = u1.x; ah[mt][3] = u1.y;
                uint2 v0 = lds64(abase + ALo);
                uint2 v1 = lds64(abase + ALo + 256);
                al[mt][0] = v0.x; al[mt][2] = v0.y; al[mt][1] = v1.x; al[mt][3] = v1.y;
            }
#pragma unroll
            for (int nt = 0; nt < 8; nt++) {
                int n8 = cw * 8 + nt;
                unsigned bbase = stg + (((j * 16 + n8) * 32) + lane) * 8;
                uint2 bh = lds64(bbase + BHo);
                uint2 bl = lds64(bbase + BLo);
#pragma unroll
                for (int mt = 0; mt < 2; mt++) {
                    mma_bf16(acc[mt][nt], ah[mt], bh.x, bh.y);
                    mma_bf16(acc[mt][nt], ah[mt], bl.x, bl.y);
                    mma_bf16(acc[mt][nt], al[mt], bh.x, bh.y);
                }
            }
        }

        if (has_next) store_A(cur ^ 1);
        CP_WAIT0();
        __syncthreads();
        cur ^= 1;
    }

    // epilogue: cols<256 -> split images; fp32 always (cols<128 feed ckv_sum)
#pragma unroll
    for (int mt = 0; mt < 2; mt++)
#pragma unroll
        for (int i = 0; i < 2; i++) {
            int r = row0 + rw * 32 + mt * 16 + i * 8 + g;
#pragma unroll
            for (int nt = 0; nt < 8; nt++) {
                int c = col0 + cw * 64 + nt * 8 + 2 * q4;
                float x = acc[mt][nt][2 * i]     + bias[c];
                float y = acc[mt][nt][2 * i + 1] + bias[c + 1];
                if (c < 256) {
                    int k = c & 127;
                    __nv_bfloat16* ih = (c < 128) ? g_T1s1h : g_T1s2h;
                    __nv_bfloat16* il = (c < 128) ? g_T1s1l : g_T1s2l;
                    split_store(ih, il, frag_off(r, k, 4), x, y);
                }
                *(float2*)(C + (size_t)r * ldc + c) = make_float2(x, y);
            }
        }
}

// ---------------- bgemm_pp ----------------
__global__ __launch_bounds__(256, 2)
void bgemm_pp(const __nv_bfloat16* __restrict__ Ah, const __nv_bfloat16* __restrict__ Al,
              const __nv_bfloat16* __restrict__ Bh, const __nv_bfloat16* __restrict__ Bl,
              int Kdim, const float* __restrict__ bias,
              float* __restrict__ C, int ldc) {
    extern __shared__ char smraw[];
    const unsigned sm0 = smem_u32(smraw);

    const int tid  = threadIdx.x;
    const int lane = tid & 31;
    const int wid  = tid >> 5;
    const int rw   = wid & 3;
    const int cw   = wid >> 2;
    const int g    = lane >> 2;
    const int q4   = lane & 3;

    const int row0 = blockIdx.y * 128, col0 = blockIdx.x * 128;
    const int P = Kdim >> 5;

    float acc[2][8][4];
#pragma unroll
    for (int mt = 0; mt < 2; mt++)
#pragma unroll
        for (int nt = 0; nt < 8; nt++)
#pragma unroll
            for (int c = 0; c < 4; c++) acc[mt][nt][c] = 0.0f;

    auto issue = [&](int buf, int p) {
        const unsigned stg = sm0 + buf * GSTAGE;
        size_t pa = ((size_t)blockIdx.y * P + p) * 4096;
        size_t pb = ((size_t)blockIdx.x * P + p) * 4096;
        unsigned da = stg + AHo + tid * 16;
        unsigned db = stg + BHo + tid * 16;
        CP_ASYNC16(da,                Ah + pa + tid * 8);
        CP_ASYNC16(da + 4096,         Ah + pa + 2048 + tid * 8);
        CP_ASYNC16(da + (ALo-AHo),        Al + pa + tid * 8);
        CP_ASYNC16(da + (ALo-AHo) + 4096, Al + pa + 2048 + tid * 8);
        CP_ASYNC16(db,                Bh + pb + tid * 8);
        CP_ASYNC16(db + 4096,         Bh + pb + 2048 + tid * 8);
        CP_ASYNC16(db + (BLo-BHo),        Bl + pb + tid * 8);
        CP_ASYNC16(db + (BLo-BHo) + 4096, Bl + pb + 2048 + tid * 8);
        CP_COMMIT();
    };

    issue(0, 0);
    CP_WAIT0();
    __syncthreads();

    int cur = 0;
    for (int p = 0; p < P; p++) {
        bool has_next = (p + 1 < P);
        if (has_next) issue(cur ^ 1, p + 1);

        const unsigned stg = sm0 + cur * GSTAGE;
#pragma unroll
        for (int j = 0; j < 2; j++) {
            unsigned ah[2][4], al[2][4];
#pragma unroll
            for (int mt = 0; mt < 2; mt++) {
                int m16 = rw * 2 + mt;
                unsigned abase = stg + ((((j * 8 + m16) * 2) * 32) + lane) * 8;
                uint2 u0 = lds64(abase + AHo);
                uint2 u1 = lds64(abase + AHo + 256);
                ah[mt][0] = u0.x; ah[mt][2] = u0.y; ah[mt][1] = u1.x; ah[mt][3] = u1.y;
                uint2 v0 = lds64(abase + ALo);
                uint2 v1 = lds64(abase + ALo + 256);
                al[mt][0] = v0.x; al[mt][2] = v0.y; al[mt][1] = v1.x; al[mt][3] = v1.y;
            }
#pragma unroll
            for (int nt = 0; nt < 8; nt++) {
                int n8 = cw * 8 + nt;
                unsigned bbase = stg + (((j * 16 + n8) * 32) + lane) * 8;
                uint2 bh = lds64(bbase + BHo);
                uint2 bl = lds64(bbase + BLo);
#pragma unroll
                for (int mt = 0; mt < 2; mt++) {
                    mma_bf16(acc[mt][nt], ah[mt], bh.x, bh.y);
                    mma_bf16(acc[mt][nt], ah[mt], bl.x, bl.y);
                    mma_bf16(acc[mt][nt], al[mt], bh.x, bh.y);
                }
            }
        }

        CP_WAIT0();
        __syncthreads();
        cur ^= 1;
    }

#pragma unroll
    for (int mt = 0; mt < 2; mt++)
#pragma unroll
        for (int i = 0; i < 2; i++) {
            int r = row0 + rw * 32 + mt * 16 + i * 8 + g;
#pragma unroll
            for (int nt = 0; nt < 8; nt++) {
                int c = col0 + cw * 64 + nt * 8 + 2 * q4;
                float2 o2;
                o2.x = acc[mt][nt][2 * i]     + bias[c];
                o2.y = acc[mt][nt][2 * i + 1] + bias[c + 1];
                *(float2*)(C + (size_t)r * ldc + c) = o2;
            }
        }
}

// ---------------- Vsum path (parallel, R15-proven): sum_s c_kv, then @ W_uv ----------------
__global__ void ckv_sum(const float* __restrict__ T1) {   // grid (32, 2), 256 thr
    __shared__ float part[2][128];
    int seg = blockIdx.x, b = blockIdx.y;
    int c = threadIdx.x & 127, p = threadIdx.x >> 7;
    const float* base = T1 + ((size_t)(b * 2048 + seg * 64 + p * 32)) * 512 + c;
    float s = 0.0f;
#pragma unroll 8
    for (int r = 0; r < 32; r++) s += base[(size_t)r * 512];
    part[p][c] = s;
    __syncthreads();
    if (p == 0)
        g_part[(b * 32 + seg) * 128 + c] = part[0][c] + part[1][c];
}

__global__ void vsum_k(const float* __restrict__ Wuv, const float* __restrict__ buv) {
    __shared__ float cs[128];
    __shared__ float red[4][128];
    int blk = blockIdx.x, b = blockIdx.y;
    int nl = threadIdx.x & 127, cp = threadIdx.x >> 7;
    if (threadIdx.x < 128) {
        float s = 0.0f;
#pragma unroll
        for (int ph = 0; ph < 32; ph++) s += g_part[(b * 32 + ph) * 128 + threadIdx.x];
        cs[threadIdx.x] = s;
    }
    __syncthreads();
    int n = blk * 128 + nl;
    float s = 0.0f;
#pragma unroll 8
    for (int c = cp * 32; c < cp * 32 + 32; c++) s += cs[c] * Wuv[c * 1024 + n];
    red[cp][nl] = s;
    __syncthreads();
    if (cp == 0)
        g_Vsum[b * 1024 + n] = 2048.0f * buv[n]
            + ((red[0][nl] + red[1][nl]) + (red[2][nl] + red[3][nl]));
}

// ---------------- rope + layout assemble (R14-proven element-wise version) ----------------
__global__ void assemble_qkv(const float* __restrict__ T1, const float* __restrict__ T2) {
    int row = blockIdx.x;
    int b = row >> 11, pos = row & 2047;
    float t = (float)pos * (1.0f / 40.0f);
    const float* t2row = T2 + (size_t)row * 2816;
    const float* t1row = T1 + (size_t)row * 512;
    const int kt = pos >> 6, rk = pos & 63;
    const int qt = pos >> 7, rq = pos & 127;
#pragma unroll
    for (int it = 0; it < 4; it++) {
        int idx = threadIdx.x + (it << 8);
        int h = idx >> 6, d = idx & 63;
        int bh = b * Hh + h;
        size_t ktile = ((size_t)bh * 32 + kt) * 4096;
        g_Vb[ktile + bfrag_off(d, rk)] = __float2bfloat16(t2row[768 + idx]);
        float qv, kv;
        if (d < 48) {
            qv = t2row[1792 + h*48 + d];
            kv = t2row[h*48 + d];
        } else {
            int j = d - 48;
            const float* xq = t2row + 2560 + h*16;
            const float* xk = t1row + 256  + h*16;
            if (j >= 8) { qv = xq[j]; kv = xk[j]; }
            else {
                int jj = j & 3;
                float ang = t * powf(10000.0f, -0.25f * (float)jj);
                float sn, cs; sincosf(ang, &sn, &cs);
                if (j < 4) { qv = xq[j]*cs - xq[j+4]*sn; kv = xk[j]*cs - xk[j+4]*sn; }
                else       { qv = xq[j]*cs + xq[j-4]*sn; kv = xk[j]*cs + xk[j-4]*sn; }
            }
        }
        size_t qoff = ((size_t)bh * 16 + qt) * 8192 + frag_off(rq, d & ~1, 2) + (d & 1);
        g_Qb[qoff] = __float2bfloat16(qv * 0.125f);
        g_Kb[ktile + bfrag_off(rk, d)] = __float2bfloat16(kv);
    }
}

// ---------------- flash attention v7: double-buffered K/V, 2 syncs/iter ----------------
// smem: QF[0,16384) KF0[16384,24576) KF1[24576,32768) VF0[32768,40960) VF1[40960,49152)
//       PS[49152,65536) RED[65536,66560)
#define QF_OFF   0
#define KF_OFF   16384
#define VF_OFF   32768
#define PS_OFF   49152
#define RED_OFF  65536
#define FLASH_SMEM 66560

__global__ __launch_bounds__(256, 2)
void flash_bf16(const __nv_bfloat16* __restrict__ Qb, const __nv_bfloat16* __restrict__ Kb,
                const __nv_bfloat16* __restrict__ Vb) {
    extern __shared__ char smraw[];
    const unsigned sm0 = smem_u32(smraw);
    const unsigned QF = sm0 + QF_OFF;
    const unsigned KF0 = sm0 + KF_OFF, VF0 = sm0 + VF_OFF, PSb = sm0 + PS_OFF;
    float* Red = (float*)(smraw + RED_OFF);

    const int tid  = threadIdx.x;
    const int lane = tid & 31;
    const int w    = tid >> 5;
    const int rw   = w & 3;
    const int cw   = w >> 2;
    const int g    = lane >> 2;
    const int q4   = lane & 3;

    const int qb = blockIdx.x, h = blockIdx.y, b = blockIdx.z;
    const int bh = b * Hh + h;
    const __nv_bfloat16* Qimg = Qb + ((size_t)bh * 16 + qb) * 8192;
    const __nv_bfloat16* Kimg = Kb + (size_t)bh * 32 * 4096;
    const __nv_bfloat16* Vimg = Vb + (size_t)bh * 32 * 4096;

    auto issueKV = [&](int t, int buf) {
        const __nv_bfloat16* ks = Kimg + (size_t)t * 4096 + tid * 8;
        const __nv_bfloat16* vs = Vimg + (size_t)t * 4096 + tid * 8;
        unsigned kd = KF0 + buf * 8192 + tid * 16;
        unsigned vd = VF0 + buf * 8192 + tid * 16;
        CP_ASYNC16(kd,        ks);
        CP_ASYNC16(kd + 4096, ks + 2048);
        CP_ASYNC16(vd,        vs);
        CP_ASYNC16(vd + 4096, vs + 2048);
        CP_COMMIT();
    };

    // prologue: Q (once) + first K/V tile
    {
        const __nv_bfloat16* src = Qimg + tid * 8;
        unsigned dst = QF + tid * 16;
        CP_ASYNC16(dst,         src);
        CP_ASYNC16(dst + 4096,  src + 2048);
        CP_ASYNC16(dst + 8192,  src + 4096);
        CP_ASYNC16(dst + 12288, src + 6144);
        CP_COMMIT();
    }
    issueKV(0, 0);
    CP_WAIT0();
    __syncthreads();

    float lsum[2][2], o[2][4][4];
#pragma unroll
    for (int mt = 0; mt < 2; mt++)
#pragma unroll
        for (int i = 0; i < 2; i++) lsum[mt][i] = 0.0f;
#pragma unroll
    for (int mt = 0; mt < 2; mt++)
#pragma unroll
        for (int nt = 0; nt < 4; nt++)
#pragma unroll
            for (int c = 0; c < 4; c++) o[mt][nt][c] = 0.0f;

    for (int kt = 0; kt < 32; kt++) {
        const int cur = kt & 1;
        const unsigned KF = KF0 + cur * 8192;
        const unsigned VF = VF0 + cur * 8192;

        // issue next K/V into the other buffer (free since iter kt-1's sync#2)
        if (kt + 1 < 32) issueKV(kt + 1, cur ^ 1);

        // ---- S = Q @ K^T ----
        float sfr[2][4][4];
#pragma unroll
        for (int mt = 0; mt < 2; mt++)
#pragma unroll
            for (int nt = 0; nt < 4; nt++)
#pragma unroll
                for (int c = 0; c < 4; c++) sfr[mt][nt][c] = 0.0f;

#pragma unroll
        for (int s = 0; s < 4; s++) {
            int p = s >> 1, j = s & 1;
            unsigned af[2][4];
#pragma unroll
            for (int mt = 0; mt < 2; mt++) {
                unsigned ab = QF + p * 8192
                            + (unsigned)((j * 8 + rw * 2 + mt) * 2) * 256 + (lane << 3);
                uint2 u0 = lds64(ab);
                uint2 u1 = lds64(ab + 256);
                af[mt][0] = u0.x; af[mt][1] = u1.x; af[mt][2] = u0.y; af[mt][3] = u1.y;
            }
#pragma unroll
            for (int nt = 0; nt < 4; nt++) {
                uint2 bf = lds64(KF + p * 4096
                                 + (unsigned)(j * 8 + cw * 4 + nt) * 256 + (lane << 3));
#pragma unroll
                for (int mt = 0; mt < 2; mt++)
                    mma_bf16(sfr[mt][nt], af[mt], bf.x, bf.y);
            }
        }

        // ---- p' = exp(s)-1, write bf16 P' image, local sums ----
#pragma unroll
        for (int mt = 0; mt < 2; mt++)
#pragma unroll
            for (int i = 0; i < 2; i++) {
#pragma unroll
                for (int jj = 0; jj < 2; jj++) {
                    float p0 = __expf(sfr[mt][2*jj][2*i])     - 1.0f;
                    float p1 = __expf(sfr[mt][2*jj][2*i+1])   - 1.0f;
                    float p2 = __expf(sfr[mt][2*jj+1][2*i])   - 1.0f;
                    float p3 = __expf(sfr[mt][2*jj+1][2*i+1]) - 1.0f;
                    lsum[mt][i] += (p0 + p1) + (p2 + p3);
                    unsigned addr = PSb + cw * 8192
                                  + (unsigned)((jj * 8 + rw * 2 + mt) * 2 + i) * 256
                                  + ((unsigned)(g * 4 + q4) << 3);
                    sts64(addr, bits2(__floats2bfloat162_rn(p0, p1)),
                                bits2(__floats2bfloat162_rn(p2, p3)));
                }
            }

        __syncthreads();     // #1: PS visible; all QK reads of KF[cur] done

        // ---- O += P' @ V ----
#pragma unroll
        for (int s = 0; s < 4; s++) {
            int p = s >> 1, j = s & 1;
            unsigned pa[2][4];
#pragma unroll
            for (int mt = 0; mt < 2; mt++) {
                unsigned ab = PSb + p * 8192
                            + (unsigned)((j * 8 + rw * 2 + mt) * 2) * 256 + (lane << 3);
                uint2 u0 = lds64(ab);
                uint2 u1 = lds64(ab + 256);
                pa[mt][0] = u0.x; pa[mt][1] = u1.x; pa[mt][2] = u0.y; pa[mt][3] = u1.y;
            }
#pragma unroll
            for (int nt = 0; nt < 4; nt++) {
                uint2 vb = lds64(VF + (unsigned)p * 4096
                                 + (unsigned)(j * 8 + cw * 4 + nt) * 256 + (lane << 3));
#pragma unroll
                for (int mt = 0; mt < 2; mt++)
                    mma_bf16(o[mt][nt], pa[mt], vb.x, vb.y);
            }
        }

        if (kt + 1 < 32) CP_WAIT0();   // next K/V landed (issued ~full iter ago)
        __syncthreads();               // #2: PS/VF[cur] free; KF/VF[nxt] visible
    }

    // ---- final denominator: l = 2048 + sum p' ----
#pragma unroll
    for (int mt = 0; mt < 2; mt++)
#pragma unroll
        for (int i = 0; i < 2; i++) {
            float s = lsum[mt][i];
            s += __shfl_xor_sync(0xffffffffu, s, 1);
            s += __shfl_xor_sync(0xffffffffu, s, 2);
            if (q4 == 0) Red[(rw*32 + mt*16 + i*8 + g)*2 + cw] = s;
        }
    __syncthreads();

    // ---- epilogue: o = (Vsum + P'V) / l, write split frag-ordered O images ----
#pragma unroll
    for (int mt = 0; mt < 2; mt++)
#pragma unroll
        for (int i = 0; i < 2; i++) {
            int rloc = rw*32 + mt*16 + i*8 + g;
            int r = b*Sq + qb*128 + rloc;
            float l = 2048.0f + Red[rloc*2] + Red[rloc*2 + 1];
            float inv = 1.0f / l;
#pragma unroll
            for (int nt = 0; nt < 4; nt++) {
                int col = cw*32 + nt*8 + 2*q4;
                float vs0 = g_Vsum[b*1024 + h*64 + col];
                float vs1 = g_Vsum[b*1024 + h*64 + col + 1];
                int k = h*64 + col;
                split_store(g_Osh, g_Osl, frag_off(r, k, 32),
                            (o[mt][nt][2*i]   + vs0) * inv,
                            (o[mt][nt][2*i+1] + vs1) * inv);
            }
        }
}

// ---------------- launch ----------------
extern "C" void kernel_launch(void* const* d_in, const int* in_sizes, int n_in,
                              void* d_out, int out_size) {
    (void)in_sizes; (void)n_in; (void)out_size;
    const float* h    = (const float*)d_in[0];
    const float* Wdkv = (const float*)d_in[1];
    const float* bdkv = (const float*)d_in[2];
    const float* Wdq  = (const float*)d_in[3];
    const float* bdq  = (const float*)d_in[4];
    const float* Wuk  = (const float*)d_in[5];
    const float* buk  = (const float*)d_in[6];
    const float* Wuv  = (const float*)d_in[7];
    const float* buv  = (const float*)d_in[8];
    const float* Wuq  = (const float*)d_in[9];
    const float* buq  = (const float*)d_in[10];
    const float* Wqr  = (const float*)d_in[11];
    const float* bqr  = (const float*)d_in[12];
    const float* Wkr  = (const float*)d_in[13];
    const float* bkr  = (const float*)d_in[14];
    const float* Wo   = (const float*)d_in[15];
    const float* bo   = (const float*)d_in[16];
    float* out = (float*)d_out;

    float *T1, *T2, *bc1, *bc2;
    __nv_bfloat16 *W1h, *W1l, *W2h, *W2l, *Woh, *Wol;
    __nv_bfloat16 *T1s1h, *T1s1l, *T1s2h, *T1s2l, *Osh, *Osl;
    __nv_bfloat16 *Qb, *Kb, *Vb;
    cudaGetSymbolAddress((void**)&T1,  g_T1);
    cudaGetSymbolAddress((void**)&T2,  g_T2);
    cudaGetSymbolAddress((void**)&bc1, g_bc1);
    cudaGetSymbolAddress((void**)&bc2, g_bc2);
    cudaGetSymbolAddress((void**)&W1h, g_W1h);
    cudaGetSymbolAddress((void**)&W1l, g_W1l);
    cudaGetSymbolAddress((void**)&W2h, g_W2h);
    cudaGetSymbolAddress((void**)&W2l, g_W2l);
    cudaGetSymbolAddress((void**)&Woh, g_Woh);
    cudaGetSymbolAddress((void**)&Wol, g_Wol);
    cudaGetSymbolAddress((void**)&T1s1h, g_T1s1h);
    cudaGetSymbolAddress((void**)&T1s1l, g_T1s1l);
    cudaGetSymbolAddress((void**)&T1s2h, g_T1s2h);
    cudaGetSymbolAddress((void**)&T1s2l, g_T1s2l);
    cudaGetSymbolAddress((void**)&Osh, g_Osh);
    cudaGetSymbolAddress((void**)&Osl, g_Osl);
    cudaGetSymbolAddress((void**)&Qb,  g_Qb);
    cudaGetSymbolAddress((void**)&Kb,  g_Kb);
    cudaGetSymbolAddress((void**)&Vb,  g_Vb);

    static int attr_set = 0;
    if (!attr_set) {
        cudaFuncSetAttribute(flash_bf16, cudaFuncAttributeMaxDynamicSharedMemorySize,
                             FLASH_SMEM);
        cudaFuncSetAttribute(bgemm_down, cudaFuncAttributeMaxDynamicSharedMemorySize,
                             GSMEM_BYTES);
        cudaFuncSetAttribute(bgemm_pp, cudaFuncAttributeMaxDynamicSharedMemorySize,
                             GSMEM_BYTES);
        attr_set = 1;
    }

    // 1) weight transpose + bf16 split (fragment-ordered) + bias pack
    wsplit_all<<<1889, dim3(32, 8)>>>(Wdkv, Wdq, Wkr, Wuk, Wuv, Wuq, Wqr, Wo,
                                      bdkv, bdq, bkr, buk, buv, buq, bqr);

    // 2) down-proj + k_rot raw
    bgemm_down<<<dim3(4, 32), 256, GSMEM_BYTES>>>(h, Dm, W1h, W1l, 1024, bc1, T1, 512);

    // 2b) Vsum path (parallel): sum_s c_kv, then mini-gemm with W_uv
    ckv_sum<<<dim3(32, 2), 256>>>(T1);
    vsum_k<<<dim3(8, 2), 512>>>(Wuv, buv);

    // 3) up-projections (K=128)
    bgemm_pp<<<dim3(14, 32), 256, GSMEM_BYTES>>>(T1s1h, T1s1l, W2h, W2l, 128, bc2, T2, 2816);
    bgemm_pp<<<dim3(8, 32), 256, GSMEM_BYTES>>>(T1s2h, T1s2l,
                                                W2h + (size_t)14*4*4096, W2l + (size_t)14*4*4096,
                                                128, bc2 + 1792, T2 + 1792, 2816);

    // 4) rope + layout (bf16 frag images)
    assemble_qkv<<<BS, 256>>>(T1, T2);

    // 5) attention (subtract-1 softmax, double-buffered K/V, 2 syncs/iter)
    flash_bf16<<<dim3(Sq/128, Hh, Bsz), 256, FLASH_SMEM>>>(Qb, Kb, Vb);

    // 6) output projection
    bgemm_pp<<<dim3(8, 32), 256, GSMEM_BYTES>>>(Osh, Osl, Woh, Wol, 1024, bo, out, 1024);
}